// round 10
// baseline (speedup 1.0000x reference)
#include <cuda_runtime.h>
#include <cuda_fp16.h>

// N=50000 nodes, D=64, E=800000 edges, HID=64.
//   Pa[n][j] = emb[n] . W1[0:64 , j] + b1[j]   (stored fp16)
//   Pb[n][j] = emb[n] . W1[64:128, j]          (stored fp16)
//   out[e]   = W2 . relu(Pa[src[e]] + Pb[dst[e]]) + b2
// R10: precompute epilogue staged through smem -> coalesced STG.128 table
//      writes (was 32 scattered STG.32/thread = ~16 lines per store instr).
//      Edge kernel = R7 exactly (best measured: 21.4us).

#define MAX_NODES 50048
#define D 64
#define HID 64

__device__ __half g_Pa[MAX_NODES * HID];   // includes b1
__device__ __half g_Pb[MAX_NODES * HID];

// ---------------------------------------------------------------------------
// Kernel 1: P = emb @ [W1a | W1b]  (50000x64 @ 64x128) via HMMA.
// Stage rows in smem (272B padded stride), then copy out coalesced.
// ---------------------------------------------------------------------------
__global__ void precompute_mma(const float* __restrict__ emb,
                               const float* __restrict__ W1,
                               const float* __restrict__ b1,
                               int n_nodes)
{
    __shared__ __align__(16) unsigned char smem_raw[36864];
    __half* As = (__half*)smem_raw;            // [128][72]
    __half* Bs = As + 128 * 72;                // [128][72]
    __half* St = (__half*)smem_raw;            // stage [128][136] (reuses As/Bs)

    const int tid = threadIdx.x;
    const int node0 = blockIdx.x * 128;

    {
        int r  = tid >> 1;
        int c0 = (tid & 1) * 32;
        int gn = node0 + r;
        __half2* dst = (__half2*)&As[r * 72 + c0];
        if (gn < n_nodes) {
            const float4* src = (const float4*)(emb + (size_t)gn * D + c0);
            #pragma unroll
            for (int q = 0; q < 8; q++) {
                float4 v = src[q];
                dst[q * 2]     = __floats2half2_rn(v.x, v.y);
                dst[q * 2 + 1] = __floats2half2_rn(v.z, v.w);
            }
        } else {
            #pragma unroll
            for (int q = 0; q < 16; q++) dst[q] = __half2half2(__float2half(0.f));
        }
    }
    for (int i = tid; i < 128 * 64; i += 256) {
        int k = i >> 7, o = i & 127;
        float w = W1[((o < 64) ? k : 64 + k) * HID + (o & 63)];
        Bs[o * 72 + k] = __float2half(w);
    }
    __syncthreads();

    const int warp = tid >> 5, lane = tid & 31;
    const int g = lane >> 2, tig = lane & 3;
    const int mrow = warp * 16;

    float acc[16][4];
    #pragma unroll
    for (int nt = 0; nt < 16; nt++)
        #pragma unroll
        for (int q = 0; q < 4; q++) acc[nt][q] = 0.f;

    #pragma unroll
    for (int kt = 0; kt < 4; kt++) {
        const __half* abase = &As[(mrow + g) * 72 + kt * 16 + tig * 2];
        unsigned int a0 = *(const unsigned int*)(abase);
        unsigned int a1 = *(const unsigned int*)(abase + 8 * 72);
        unsigned int a2 = *(const unsigned int*)(abase + 8);
        unsigned int a3 = *(const unsigned int*)(abase + 8 * 72 + 8);
        #pragma unroll
        for (int nt = 0; nt < 16; nt++) {
            const __half* bbase = &Bs[(nt * 8 + g) * 72 + kt * 16 + tig * 2];
            unsigned int b0 = *(const unsigned int*)(bbase);
            unsigned int b1r = *(const unsigned int*)(bbase + 8);
            asm volatile(
                "mma.sync.aligned.m16n8k16.row.col.f32.f16.f16.f32 "
                "{%0,%1,%2,%3}, {%4,%5,%6,%7}, {%8,%9}, {%0,%1,%2,%3};"
                : "+f"(acc[nt][0]), "+f"(acc[nt][1]), "+f"(acc[nt][2]), "+f"(acc[nt][3])
                : "r"(a0), "r"(a1), "r"(a2), "r"(a3), "r"(b0), "r"(b1r));
        }
    }

    __syncthreads();   // all fragment LDS done; safe to overwrite As/Bs with St

    // Stage: St[r][o] halves, row stride 136 (272B) -> STS.32 conflict-free:
    // bank = (4g + tig + 4nt) mod 32 covers all 32 banks per nt.
    {
        const int nc = tig * 2;
        const int r0 = mrow + g;
        const int r1 = r0 + 8;
        #pragma unroll
        for (int nt = 0; nt < 16; nt++) {
            int o = nt * 8 + nc;
            float bx = 0.f, by = 0.f;
            if (o < 64) { bx = b1[o]; by = b1[o + 1]; }
            *(__half2*)(St + r0 * 136 + o) =
                __floats2half2_rn(acc[nt][0] + bx, acc[nt][1] + by);
            *(__half2*)(St + r1 * 136 + o) =
                __floats2half2_rn(acc[nt][2] + bx, acc[nt][3] + by);
        }
    }
    __syncthreads();

    // Coalesced copy out: warp writes 4 consecutive node rows (512B) per table.
    for (int seg = tid; seg < 1024; seg += 256) {
        int r = seg >> 3, c = seg & 7;        // row, 16B-segment within row
        int gn = node0 + r;
        if (gn < n_nodes) {
            uint4 va = *(const uint4*)(St + r * 136 + c * 8);
            *(uint4*)(g_Pa + (size_t)gn * HID + c * 8) = va;
            uint4 vb = *(const uint4*)(St + r * 136 + 64 + c * 8);
            *(uint4*)(g_Pb + (size_t)gn * HID + c * 8) = vb;
        }
    }
}

// ---------------------------------------------------------------------------
// Kernel 2: gather + relu + dot(W2). 8 lanes/group, 4 edges/group, 16/warp.
// (R7 config - best measured.)
// ---------------------------------------------------------------------------
__device__ __forceinline__ float edge_dot(uint4 av, uint4 bv,
                                          float4 w0, float4 w1)
{
    const __half2 z2 = __half2half2(__float2half(0.f));
    __half2 s0 = __hmax2(__hadd2(*(__half2*)&av.x, *(__half2*)&bv.x), z2);
    __half2 s1 = __hmax2(__hadd2(*(__half2*)&av.y, *(__half2*)&bv.y), z2);
    __half2 s2 = __hmax2(__hadd2(*(__half2*)&av.z, *(__half2*)&bv.z), z2);
    __half2 s3 = __hmax2(__hadd2(*(__half2*)&av.w, *(__half2*)&bv.w), z2);
    float2 f0 = __half22float2(s0);
    float2 f1 = __half22float2(s1);
    float2 f2 = __half22float2(s2);
    float2 f3 = __half22float2(s3);
    return f0.x * w0.x + f0.y * w0.y
         + f1.x * w0.z + f1.y * w0.w
         + f2.x * w1.x + f2.y * w1.y
         + f3.x * w1.z + f3.y * w1.w;
}

__global__ void __launch_bounds__(256)
edge_kernel(const int* __restrict__ ei,
            const float* __restrict__ W2,
            const float* __restrict__ b2,
            float* __restrict__ out,
            int E)
{
    int gtid = blockIdx.x * blockDim.x + threadIdx.x;
    int warp = gtid >> 5;
    int lane = threadIdx.x & 31;
    int t = lane & 7;                // slot within edge group
    int g = lane >> 3;               // edge group 0..3

    float4 w0 = *(const float4*)(W2 + (t << 3));
    float4 w1 = *(const float4*)(W2 + (t << 3) + 4);
    float b2v = __ldg(b2);

    int e0 = warp * 16 + g * 4;      // first of 4 consecutive edges
    int ec = e0;
    if (ec + 4 > E) ec = (E >= 4) ? (E - 4) : 0;   // clamp (overlap recompute ok)

    // Index loads: every lane of the group reads the same int4 -> 1 line, bcast.
    int4 sv, dv;
    if (((E | ec) & 3) == 0) {
        sv = *(const int4*)(ei + ec);
        dv = *(const int4*)(ei + E + ec);
    } else {
        sv.x = ei[ec];     sv.y = ei[ec + 1];     sv.z = ei[ec + 2];     sv.w = ei[ec + 3];
        dv.x = ei[E + ec]; dv.y = ei[E + ec + 1]; dv.z = ei[E + ec + 2]; dv.w = ei[E + ec + 3];
    }

    // 8 independent 128B gathers in flight
    uint4 A0 = ((const uint4*)(g_Pa + (size_t)sv.x * HID))[t];
    uint4 B0 = ((const uint4*)(g_Pb + (size_t)dv.x * HID))[t];
    uint4 A1 = ((const uint4*)(g_Pa + (size_t)sv.y * HID))[t];
    uint4 B1 = ((const uint4*)(g_Pb + (size_t)dv.y * HID))[t];
    uint4 A2 = ((const uint4*)(g_Pa + (size_t)sv.z * HID))[t];
    uint4 B2 = ((const uint4*)(g_Pb + (size_t)dv.z * HID))[t];
    uint4 A3 = ((const uint4*)(g_Pa + (size_t)sv.w * HID))[t];
    uint4 B3 = ((const uint4*)(g_Pb + (size_t)dv.w * HID))[t];

    float p0 = edge_dot(A0, B0, w0, w1);
    float p1 = edge_dot(A1, B1, w0, w1);
    float p2 = edge_dot(A2, B2, w0, w1);
    float p3 = edge_dot(A3, B3, w0, w1);

    #pragma unroll
    for (int m = 4; m >= 1; m >>= 1) {
        p0 += __shfl_xor_sync(0xffffffffu, p0, m);
        p1 += __shfl_xor_sync(0xffffffffu, p1, m);
        p2 += __shfl_xor_sync(0xffffffffu, p2, m);
        p3 += __shfl_xor_sync(0xffffffffu, p3, m);
    }

    if (t == 0 && ec < E) {
        if ((ec & 3) == 0 && ec + 4 <= E) {
            float4 r;
            r.x = p0 + b2v; r.y = p1 + b2v; r.z = p2 + b2v; r.w = p3 + b2v;
            *(float4*)(out + ec) = r;        // duplicates on clamp are identical
        } else {
            if (ec < E)     out[ec]     = p0 + b2v;
            if (ec + 1 < E) out[ec + 1] = p1 + b2v;
            if (ec + 2 < E) out[ec + 2] = p2 + b2v;
            if (ec + 3 < E) out[ec + 3] = p3 + b2v;
        }
    }
}

// ---------------------------------------------------------------------------
extern "C" void kernel_launch(void* const* d_in, const int* in_sizes, int n_in,
                              void* d_out, int out_size)
{
    const float* emb = (const float*)d_in[0];
    const int*   ei  = (const int*)d_in[1];     // int32 (JAX x64 disabled)
    const float* W1  = (const float*)d_in[2];
    const float* b1  = (const float*)d_in[3];
    const float* W2  = (const float*)d_in[4];
    const float* b2  = (const float*)d_in[5];
    float*       out = (float*)d_out;

    int n_nodes = in_sizes[0] / D;        // 50000
    int E       = in_sizes[1] / 2;        // 800000

    int pre_blocks = (n_nodes + 127) / 128;
    precompute_mma<<<pre_blocks, 256>>>(emb, W1, b1, n_nodes);

    long long warps = ((long long)E + 15) / 16;
    long long threads = warps * 32;
    int blocks = (int)((threads + 255) / 256);
    edge_kernel<<<blocks, 256>>>(ei, W2, b2, out, E);
}

// round 11
// speedup vs baseline: 1.0087x; 1.0087x over previous
#include <cuda_runtime.h>
#include <cuda_fp16.h>

// N=50000 nodes, D=64, E=800000 edges, HID=64.
//   Pa[n][j] = emb[n] . W1[0:64 , j] + b1[j]   (stored fp16)
//   Pb[n][j] = emb[n] . W1[64:128, j]          (stored fp16)
//   out[e]   = W2 . relu(Pa[src[e]] + Pb[dst[e]]) + b2
// R11: single persistent kernel: precompute phase + device-wide ticket barrier
//      + edge phase. Removes the second launch and inter-kernel gap (the
//      residual between ncu edge time and wallclock total swung 7.8-13.4us
//      across rounds with identical precompute code).

#define MAX_NODES 50048
#define D 64
#define HID 64
#define GRID_BLOCKS 592      // 4 blocks/SM x 148 SMs -> co-resident guaranteed

__device__ __half g_Pa[MAX_NODES * HID];   // includes b1
__device__ __half g_Pb[MAX_NODES * HID];
__device__ unsigned int g_bar = 0;         // monotonic ticket counter (replay-safe)

__device__ __forceinline__ float edge_dot(uint4 av, uint4 bv,
                                          float4 w0, float4 w1)
{
    const __half2 z2 = __half2half2(__float2half(0.f));
    __half2 s0 = __hmax2(__hadd2(*(__half2*)&av.x, *(__half2*)&bv.x), z2);
    __half2 s1 = __hmax2(__hadd2(*(__half2*)&av.y, *(__half2*)&bv.y), z2);
    __half2 s2 = __hmax2(__hadd2(*(__half2*)&av.z, *(__half2*)&bv.z), z2);
    __half2 s3 = __hmax2(__hadd2(*(__half2*)&av.w, *(__half2*)&bv.w), z2);
    float2 f0 = __half22float2(s0);
    float2 f1 = __half22float2(s1);
    float2 f2 = __half22float2(s2);
    float2 f3 = __half22float2(s3);
    return f0.x * w0.x + f0.y * w0.y
         + f1.x * w0.z + f1.y * w0.w
         + f2.x * w1.x + f2.y * w1.y
         + f3.x * w1.z + f3.y * w1.w;
}

__global__ void __launch_bounds__(256, 4)
fused_kernel(const float* __restrict__ emb,
             const int*   __restrict__ ei,
             const float* __restrict__ W1,
             const float* __restrict__ b1,
             const float* __restrict__ W2,
             const float* __restrict__ b2,
             float*       __restrict__ out,
             int n_nodes, int E)
{
    // Phase-1 smem: As[64][72] + Bs[128][72] = 27648B; St[64][136] reuses it.
    __shared__ __align__(16) unsigned char smem_raw[27648];
    __half* As = (__half*)smem_raw;            // [64][72]
    __half* Bs = As + 64 * 72;                 // [128][72]
    __half* St = (__half*)smem_raw;            // [64][136]

    const int tid  = threadIdx.x;
    const int warp = tid >> 5, lane = tid & 31;

    // ===================== Phase 1: precompute tables =====================
    const int ntiles = (n_nodes + 63) >> 6;
    for (int tile = blockIdx.x; tile < ntiles; tile += gridDim.x) {
        const int node0 = tile << 6;
        __syncthreads();   // previous iter's St reads done before overwriting

        // Load emb tile (64 x 64 fp32 -> fp16). Coalesced float4 reads.
        {
            int r  = tid >> 2;            // 0..63
            int c0 = (tid & 3) << 4;      // 0,16,32,48
            int gn = node0 + r;
            __half2* dst = (__half2*)&As[r * 72 + c0];
            if (gn < n_nodes) {
                const float4* src = (const float4*)(emb + (size_t)gn * D + c0);
                #pragma unroll
                for (int q = 0; q < 4; q++) {
                    float4 v = src[q];
                    dst[q * 2]     = __floats2half2_rn(v.x, v.y);
                    dst[q * 2 + 1] = __floats2half2_rn(v.z, v.w);
                }
            } else {
                #pragma unroll
                for (int q = 0; q < 8; q++) dst[q] = __half2half2(__float2half(0.f));
            }
        }
        // Load W1 transposed: Bs[o][k]; o<64 -> W1a[:,o], o>=64 -> W1b[:,o-64]
        for (int i = tid; i < 128 * 64; i += 256) {
            int k = i >> 7, o = i & 127;
            float w = W1[((o < 64) ? k : 64 + k) * HID + (o & 63)];
            Bs[o * 72 + k] = __float2half(w);
        }
        __syncthreads();

        // MMA: warp w -> rows mrow=(w&3)*16, out half hb=(w>>2)*64 (8 n-tiles).
        const int g4 = lane >> 2, tig = lane & 3;
        const int mrow = (warp & 3) * 16;
        const int hb   = (warp >> 2) * 64;

        float acc[8][4];
        #pragma unroll
        for (int nt = 0; nt < 8; nt++)
            #pragma unroll
            for (int q = 0; q < 4; q++) acc[nt][q] = 0.f;

        #pragma unroll
        for (int kt = 0; kt < 4; kt++) {
            const __half* abase = &As[(mrow + g4) * 72 + kt * 16 + tig * 2];
            unsigned int a0 = *(const unsigned int*)(abase);
            unsigned int a1 = *(const unsigned int*)(abase + 8 * 72);
            unsigned int a2 = *(const unsigned int*)(abase + 8);
            unsigned int a3 = *(const unsigned int*)(abase + 8 * 72 + 8);
            #pragma unroll
            for (int nt = 0; nt < 8; nt++) {
                const __half* bbase = &Bs[(hb + nt * 8 + g4) * 72 + kt * 16 + tig * 2];
                unsigned int b0  = *(const unsigned int*)(bbase);
                unsigned int b1r = *(const unsigned int*)(bbase + 8);
                asm volatile(
                    "mma.sync.aligned.m16n8k16.row.col.f32.f16.f16.f32 "
                    "{%0,%1,%2,%3}, {%4,%5,%6,%7}, {%8,%9}, {%0,%1,%2,%3};"
                    : "+f"(acc[nt][0]), "+f"(acc[nt][1]), "+f"(acc[nt][2]), "+f"(acc[nt][3])
                    : "r"(a0), "r"(a1), "r"(a2), "r"(a3), "r"(b0), "r"(b1r));
            }
        }
        __syncthreads();   // fragment LDS done; safe to overwrite with St

        // Stage rows (272B stride; STS.32 conflict-free: bank=4g4+tig+4nt mod 32).
        {
            const int r0 = mrow + g4;
            const int r1 = r0 + 8;
            #pragma unroll
            for (int nt = 0; nt < 8; nt++) {
                int o = hb + nt * 8 + tig * 2;
                float bx = 0.f, by = 0.f;
                if (o < 64) { bx = b1[o]; by = b1[o + 1]; }
                *(__half2*)(St + r0 * 136 + o) =
                    __floats2half2_rn(acc[nt][0] + bx, acc[nt][1] + by);
                *(__half2*)(St + r1 * 136 + o) =
                    __floats2half2_rn(acc[nt][2] + bx, acc[nt][3] + by);
            }
        }
        __syncthreads();

        // Coalesced copy out: 64 rows x 8 x 16B per table.
        for (int seg = tid; seg < 512; seg += 256) {
            int r = seg >> 3, c = seg & 7;
            int gn = node0 + r;
            if (gn < n_nodes) {
                *(uint4*)(g_Pa + (size_t)gn * HID + c * 8) =
                    *(const uint4*)(St + r * 136 + c * 8);
                *(uint4*)(g_Pb + (size_t)gn * HID + c * 8) =
                    *(const uint4*)(St + r * 136 + 64 + c * 8);
            }
        }
    }

    // ===================== Device-wide ticket barrier =====================
    __threadfence();
    __syncthreads();
    if (tid == 0) {
        unsigned int ticket = atomicAdd(&g_bar, 1u);
        unsigned int target = (ticket / gridDim.x + 1u) * gridDim.x;
        while (*(volatile unsigned int*)&g_bar < target) { }
    }
    __syncthreads();
    __threadfence();

    // ===================== Phase 2: edge MLP =====================
    const int t = lane & 7;          // slot within 8-lane edge group
    const int g = lane >> 3;         // edge group 0..3

    float4 w0 = *(const float4*)(W2 + (t << 3));
    float4 w1 = *(const float4*)(W2 + (t << 3) + 4);
    float b2v = __ldg(b2);

    const int nwarps = gridDim.x * (blockDim.x >> 5);
    const int wg = blockIdx.x * (blockDim.x >> 5) + warp;

    for (int base = wg * 16; base < E; base += nwarps * 16) {
        int ec = base + g * 4;
        if (ec + 4 > E) ec = (E >= 4) ? (E - 4) : 0;   // clamp; recompute ok

        int4 sv, dv;
        if (((E | ec) & 3) == 0) {
            sv = *(const int4*)(ei + ec);              // broadcast in group
            dv = *(const int4*)(ei + E + ec);
        } else {
            sv.x = ei[ec];     sv.y = ei[ec + 1];     sv.z = ei[ec + 2];     sv.w = ei[ec + 3];
            dv.x = ei[E + ec]; dv.y = ei[E + ec + 1]; dv.z = ei[E + ec + 2]; dv.w = ei[E + ec + 3];
        }

        uint4 A0 = ((const uint4*)(g_Pa + (size_t)sv.x * HID))[t];
        uint4 B0 = ((const uint4*)(g_Pb + (size_t)dv.x * HID))[t];
        uint4 A1 = ((const uint4*)(g_Pa + (size_t)sv.y * HID))[t];
        uint4 B1 = ((const uint4*)(g_Pb + (size_t)dv.y * HID))[t];
        uint4 A2 = ((const uint4*)(g_Pa + (size_t)sv.z * HID))[t];
        uint4 B2 = ((const uint4*)(g_Pb + (size_t)dv.z * HID))[t];
        uint4 A3 = ((const uint4*)(g_Pa + (size_t)sv.w * HID))[t];
        uint4 B3 = ((const uint4*)(g_Pb + (size_t)dv.w * HID))[t];

        float p0 = edge_dot(A0, B0, w0, w1);
        float p1 = edge_dot(A1, B1, w0, w1);
        float p2 = edge_dot(A2, B2, w0, w1);
        float p3 = edge_dot(A3, B3, w0, w1);

        #pragma unroll
        for (int m = 4; m >= 1; m >>= 1) {
            p0 += __shfl_xor_sync(0xffffffffu, p0, m);
            p1 += __shfl_xor_sync(0xffffffffu, p1, m);
            p2 += __shfl_xor_sync(0xffffffffu, p2, m);
            p3 += __shfl_xor_sync(0xffffffffu, p3, m);
        }

        if (t == 0 && ec < E) {
            if ((ec & 3) == 0 && ec + 4 <= E) {
                float4 r;
                r.x = p0 + b2v; r.y = p1 + b2v; r.z = p2 + b2v; r.w = p3 + b2v;
                *(float4*)(out + ec) = r;      // clamp duplicates identical
            } else {
                if (ec < E)     out[ec]     = p0 + b2v;
                if (ec + 1 < E) out[ec + 1] = p1 + b2v;
                if (ec + 2 < E) out[ec + 2] = p2 + b2v;
                if (ec + 3 < E) out[ec + 3] = p3 + b2v;
            }
        }
    }
}

// ---------------------------------------------------------------------------
extern "C" void kernel_launch(void* const* d_in, const int* in_sizes, int n_in,
                              void* d_out, int out_size)
{
    const float* emb = (const float*)d_in[0];
    const int*   ei  = (const int*)d_in[1];     // int32 (JAX x64 disabled)
    const float* W1  = (const float*)d_in[2];
    const float* b1  = (const float*)d_in[3];
    const float* W2  = (const float*)d_in[4];
    const float* b2  = (const float*)d_in[5];
    float*       out = (float*)d_out;

    int n_nodes = in_sizes[0] / D;        // 50000
    int E       = in_sizes[1] / 2;        // 800000

    fused_kernel<<<GRID_BLOCKS, 256>>>(emb, ei, W1, b1, W2, b2, out, n_nodes, E);
}